// round 1
// baseline (speedup 1.0000x reference)
#include <cuda_runtime.h>
#include <math.h>

#define NN 524288
#define NE 2097152
#define NF 65536
#define NM 8192
#define DD 128
#define HH 256
#define EXP 8
#define NT 3

// ---------------- scratch (device globals; no allocation allowed) -------------
__device__ float g_h[(size_t)NN * DD];
__device__ float g_agg[(size_t)NN * DD];
__device__ float g_tmp[(size_t)NN * DD];
__device__ float g_frag[(size_t)NF * DD];
__device__ float g_moe[(size_t)NF * DD];
__device__ float g_a1[(size_t)2 * NF * HH];
__device__ float g_a2[(size_t)2 * NF * HH];
__device__ float g_outs[(size_t)2 * NF * DD];
__device__ float g_mol[(size_t)NM * DD];
__device__ int   g_topidx[2 * NF];
__device__ float g_topw[2 * NF];
__device__ int   g_blockcnt[256 * EXP];
__device__ int   g_blockbase[256 * EXP];
__device__ int   g_offs[EXP + 1];
__device__ int   g_list[2 * NF];
__device__ float g_wsum[EXP];

// ---------------- edge scatter-add: agg[dst] += h[src] ----------------------
__global__ void edge_k(const int* __restrict__ src, const int* __restrict__ dst,
                       const float* __restrict__ h, float* __restrict__ agg)
{
    int e = blockIdx.x * 8 + (threadIdx.x >> 5);
    int c = threadIdx.x & 31;
    if (e >= NE) return;
    int s = src[e];
    int d = dst[e];
    float4 v = ((const float4*)(h + (size_t)s * DD))[c];
    float* ap = agg + (size_t)d * DD + c * 4;
    atomicAdd(ap + 0, v.x);
    atomicAdd(ap + 1, v.y);
    atomicAdd(ap + 2, v.z);
    atomicAdd(ap + 3, v.w);
}

// ---------------- generic tiled SGEMM with fused epilogues -------------------
// C[out] = EPI(A' @ W + b), A' = (A2 ? (1+eps)*A + A2 : A)
// EPI 0: relu    1: bn(scale=bnscale*gamma, shift=beta) + relu
// EPI 2: exact gelu   3: none
// Optional gather: list/offs per blockIdx.z (expert); entry=orow, inRow=orow>>inShift
#define BM 128
#define BN 128
#define BKK 16

template <int EPI>
__global__ void __launch_bounds__(256, 2) gemm_k(
    const float* __restrict__ A,
    const float* __restrict__ A2,
    const float* __restrict__ epsP,
    const float* __restrict__ W0, int wStride,
    const float* __restrict__ b0, int bStride,
    const float* __restrict__ gmma, const float* __restrict__ bta, float bnscale,
    float* __restrict__ C,
    int M, int K, int N,
    const int* __restrict__ list, const int* __restrict__ offs, int inShift)
{
    int z = blockIdx.z;
    int mrows = M;
    const int* lst = nullptr;
    if (offs) {
        int base = offs[z];
        mrows = offs[z + 1] - base;
        lst = list + base;
    }
    int m0 = blockIdx.x * BM;
    if (m0 >= mrows) return;
    int n0 = blockIdx.y * BN;

    const float* W  = W0 + (size_t)z * wStride;
    const float* Bv = b0 + (size_t)z * bStride;

    __shared__ float As[BKK][BM + 4];
    __shared__ float Bs[BKK][BN];

    int tid = threadIdx.x;
    int tx = tid & 15, ty = tid >> 4;

    float acc[8][8];
#pragma unroll
    for (int i = 0; i < 8; i++)
#pragma unroll
        for (int j = 0; j < 8; j++) acc[i][j] = 0.f;

    float alpha = 1.0f;
    if (A2) alpha = 1.0f + *epsP;

    for (int k0 = 0; k0 < K; k0 += BKK) {
#pragma unroll
        for (int l = 0; l < 2; l++) {
            int id  = tid + l * 256;       // 0..511
            int row = id >> 2;             // 0..127
            int kq  = (id & 3) * 4;        // 0,4,8,12
            int gm  = m0 + row;
            float4 v = make_float4(0.f, 0.f, 0.f, 0.f);
            if (gm < mrows) {
                int inRow = lst ? (lst[gm] >> inShift) : gm;
                v = *(const float4*)(A + (size_t)inRow * K + k0 + kq);
                if (A2) {
                    float4 w = *(const float4*)(A2 + (size_t)inRow * K + k0 + kq);
                    v.x = alpha * v.x + w.x;
                    v.y = alpha * v.y + w.y;
                    v.z = alpha * v.z + w.z;
                    v.w = alpha * v.w + w.w;
                }
            }
            As[kq + 0][row] = v.x;
            As[kq + 1][row] = v.y;
            As[kq + 2][row] = v.z;
            As[kq + 3][row] = v.w;
        }
#pragma unroll
        for (int l = 0; l < 2; l++) {
            int id = tid + l * 256;
            int kr = id >> 5;              // 0..15
            int nq = (id & 31) * 4;
            *(float4*)&Bs[kr][nq] = *(const float4*)(W + (size_t)(k0 + kr) * N + n0 + nq);
        }
        __syncthreads();
#pragma unroll
        for (int kk = 0; kk < BKK; kk++) {
            float a[8], b[8];
            *(float4*)&a[0] = *(const float4*)&As[kk][ty * 8];
            *(float4*)&a[4] = *(const float4*)&As[kk][ty * 8 + 4];
            *(float4*)&b[0] = *(const float4*)&Bs[kk][tx * 8];
            *(float4*)&b[4] = *(const float4*)&Bs[kk][tx * 8 + 4];
#pragma unroll
            for (int i = 0; i < 8; i++)
#pragma unroll
                for (int j = 0; j < 8; j++) acc[i][j] += a[i] * b[j];
        }
        __syncthreads();
    }

#pragma unroll
    for (int i = 0; i < 8; i++) {
        int gm = m0 + ty * 8 + i;
        if (gm >= mrows) continue;
        int outRow = lst ? lst[gm] : gm;
        float* cp = C + (size_t)outRow * N + n0 + tx * 8;
        float o[8];
#pragma unroll
        for (int j = 0; j < 8; j++) {
            int n = n0 + tx * 8 + j;
            float v = acc[i][j] + Bv[n];
            if (EPI == 0) {
                v = fmaxf(v, 0.f);
            } else if (EPI == 1) {
                v = v * (bnscale * gmma[n]) + bta[n];
                v = fmaxf(v, 0.f);
            } else if (EPI == 2) {
                v = 0.5f * v * (1.f + erff(v * 0.70710678118654752f));
            }
            o[j] = v;
        }
        *(float4*)cp       = *(float4*)&o[0];
        *(float4*)(cp + 4) = *(float4*)&o[4];
    }
}

// ---------------- segment mean (sorted segment ids, warp per segment) --------
__global__ void seg_mean_k(const float* __restrict__ vals, const int* __restrict__ seg,
                           int nItems, float* __restrict__ out, int nSeg)
{
    int w = (blockIdx.x * blockDim.x + threadIdx.x) >> 5;
    int lane = threadIdx.x & 31;
    if (w >= nSeg) return;
    int lo = 0, hi = nItems;
    while (lo < hi) { int mid = (lo + hi) >> 1; if (seg[mid] < w) lo = mid + 1; else hi = mid; }
    int start = lo;
    hi = nItems;
    while (lo < hi) { int mid = (lo + hi) >> 1; if (seg[mid] < w + 1) lo = mid + 1; else hi = mid; }
    int end = lo;
    float4 s = make_float4(0.f, 0.f, 0.f, 0.f);
    for (int r = start; r < end; r++) {
        float4 v = ((const float4*)(vals + (size_t)r * DD))[lane];
        s.x += v.x; s.y += v.y; s.z += v.z; s.w += v.w;
    }
    float inv = 1.f / fmaxf((float)(end - start), 1.f);
    s.x *= inv; s.y *= inv; s.z *= inv; s.w *= inv;
    ((float4*)(out + (size_t)w * DD))[lane] = s;
}

// ---------------- router: logits, top-2, softmax weights ---------------------
__global__ void router_k(const float* __restrict__ frag, const float* __restrict__ gw)
{
    int w = (blockIdx.x * blockDim.x + threadIdx.x) >> 5;
    int lane = threadIdx.x & 31;
    if (w >= NF) return;
    float4 fv = ((const float4*)(frag + (size_t)w * DD))[lane];
    float a[4] = {fv.x, fv.y, fv.z, fv.w};
    float l[EXP];
#pragma unroll
    for (int e = 0; e < EXP; e++) l[e] = 0.f;
    int k0 = lane * 4;
#pragma unroll
    for (int j = 0; j < 4; j++) {
        const float* gr = gw + (k0 + j) * EXP;
#pragma unroll
        for (int e = 0; e < EXP; e++) l[e] += a[j] * gr[e];
    }
#pragma unroll
    for (int off = 16; off; off >>= 1)
#pragma unroll
        for (int e = 0; e < EXP; e++) l[e] += __shfl_down_sync(0xffffffffu, l[e], off);
    if (lane == 0) {
        int i1 = 0;
#pragma unroll
        for (int e = 1; e < EXP; e++) if (l[e] > l[i1]) i1 = e;
        int i2 = (i1 == 0) ? 1 : 0;
#pragma unroll
        for (int e = 0; e < EXP; e++) if (e != i1 && l[e] > l[i2]) i2 = e;
        float d = expf(l[i2] - l[i1]);
        float z = 1.f + d;
        g_topidx[2 * w] = i1;
        g_topidx[2 * w + 1] = i2;
        g_topw[2 * w] = 1.f / z;
        g_topw[2 * w + 1] = d / z;
    }
}

// ---------------- MoE dispatch build: histogram / scan / scatter -------------
__global__ void histo_k()
{
    __shared__ int sc[EXP];
    __shared__ float sw[EXP];
    int t = threadIdx.x, b = blockIdx.x;
    if (t < EXP) { sc[t] = 0; sw[t] = 0.f; }
    __syncthreads();
    int f = b * 256 + t;
    int e0 = g_topidx[2 * f], e1 = g_topidx[2 * f + 1];
    atomicAdd(&sc[e0], 1);
    atomicAdd(&sc[e1], 1);
    atomicAdd(&sw[e0], g_topw[2 * f]);
    atomicAdd(&sw[e1], g_topw[2 * f + 1]);
    __syncthreads();
    if (t < EXP) {
        g_blockcnt[b * EXP + t] = sc[t];
        atomicAdd(&g_wsum[t], sw[t]);
    }
}

__global__ void scan_k()
{
    __shared__ int tot[EXP];
    int e = threadIdx.x;
    if (e < EXP) {
        int s = 0;
        for (int b = 0; b < 256; b++) s += g_blockcnt[b * EXP + e];
        tot[e] = s;
    }
    __syncthreads();
    if (e == 0) {
        int run = 0;
        for (int i = 0; i < EXP; i++) { g_offs[i] = run; run += tot[i]; }
        g_offs[EXP] = run;
    }
    __syncthreads();
    if (e < EXP) {
        int run = g_offs[e];
        for (int b = 0; b < 256; b++) { g_blockbase[b * EXP + e] = run; run += g_blockcnt[b * EXP + e]; }
    }
}

__global__ void scatter_k()
{
    __shared__ int sc[EXP];
    int t = threadIdx.x, b = blockIdx.x;
    if (t < EXP) sc[t] = 0;
    __syncthreads();
    int f = b * 256 + t;
    int e0 = g_topidx[2 * f];
    int p0 = atomicAdd(&sc[e0], 1);
    int e1 = g_topidx[2 * f + 1];
    int p1 = atomicAdd(&sc[e1], 1);
    g_list[g_blockbase[b * EXP + e0] + p0] = 2 * f;
    g_list[g_blockbase[b * EXP + e1] + p1] = 2 * f + 1;
}

// ---------------- combine top-2 expert outputs -------------------------------
__global__ void combine_k()
{
    int t = blockIdx.x * blockDim.x + threadIdx.x;
    int f = t >> 5;
    int c = t & 31;
    float w0 = g_topw[2 * f], w1 = g_topw[2 * f + 1];
    float4 a = ((const float4*)(g_outs + (size_t)(2 * f) * DD))[c];
    float4 b = ((const float4*)(g_outs + (size_t)(2 * f + 1) * DD))[c];
    float4 r;
    r.x = w0 * a.x + w1 * b.x;
    r.y = w0 * a.y + w1 * b.y;
    r.z = w0 * a.z + w1 * b.z;
    r.w = w0 * a.w + w1 * b.w;
    ((float4*)(g_moe + (size_t)f * DD))[c] = r;
}

// ---------------- task heads -------------------------------------------------
__global__ void heads_k(const float* __restrict__ mol,
                        const float* __restrict__ hw1, const float* __restrict__ hb1,
                        const float* __restrict__ hw2, const float* __restrict__ hb2,
                        float* __restrict__ out)
{
    int m = blockIdx.x;
    int j = threadIdx.x; // 64 threads
    __shared__ float emb[DD];
    __shared__ float red[2];
    emb[j] = mol[(size_t)m * DD + j];
    emb[j + 64] = mol[(size_t)m * DD + 64 + j];
    __syncthreads();
    for (int t = 0; t < NT; t++) {
        float p = hb1[t * 64 + j];
        const float* w = hw1 + (size_t)t * DD * 64 + j;
#pragma unroll 4
        for (int d = 0; d < DD; d++) p += emb[d] * w[(size_t)d * 64];
        p = fmaxf(p, 0.f);
        float s = p * hw2[t * 64 + j];
#pragma unroll
        for (int off = 16; off; off >>= 1) s += __shfl_down_sync(0xffffffffu, s, off);
        if ((j & 31) == 0) red[j >> 5] = s;
        __syncthreads();
        if (j == 0) out[m * NT + t] = red[0] + red[1] + hb2[t];
        __syncthreads();
    }
}

// ---------------- load-balance loss ------------------------------------------
__global__ void lb_k(float* __restrict__ out, int out_size)
{
    if (out_size > NM * NT) {
        float s = 0.f;
        for (int e = 0; e < EXP; e++) {
            float l = g_wsum[e] / (float)NF;
            s += l * l;
        }
        out[NM * NT] = (float)EXP * s;
    }
}

// ---------------- launch -----------------------------------------------------
extern "C" void kernel_launch(void* const* d_in, const int* in_sizes, int n_in,
                              void* d_out, int out_size)
{
    const float* x        = (const float*)d_in[0];
    const float* gin_w1   = (const float*)d_in[1];
    const float* gin_b1   = (const float*)d_in[2];
    const float* gin_w2   = (const float*)d_in[3];
    const float* gin_b2   = (const float*)d_in[4];
    const float* gin_eps  = (const float*)d_in[5];
    const float* bn_gamma = (const float*)d_in[6];
    const float* bn_beta  = (const float*)d_in[7];
    const float* gate_w   = (const float*)d_in[8];
    const float* ew1      = (const float*)d_in[9];
    const float* eb1      = (const float*)d_in[10];
    const float* ew2      = (const float*)d_in[11];
    const float* eb2      = (const float*)d_in[12];
    const float* ew3      = (const float*)d_in[13];
    const float* eb3      = (const float*)d_in[14];
    const float* hw1      = (const float*)d_in[15];
    const float* hb1      = (const float*)d_in[16];
    const float* hw2      = (const float*)d_in[17];
    const float* hb2      = (const float*)d_in[18];
    const int*   edge     = (const int*)d_in[19];
    const int*   node2frag= (const int*)d_in[20];
    const int*   mol_idx  = (const int*)d_in[21];
    (void)in_sizes; (void)n_in;

    float *hP, *aggP, *tmpP, *fragP, *moeP, *a1P, *a2P, *outsP, *molP, *wsumP;
    int *listP, *offsP;
    cudaGetSymbolAddress((void**)&hP, g_h);
    cudaGetSymbolAddress((void**)&aggP, g_agg);
    cudaGetSymbolAddress((void**)&tmpP, g_tmp);
    cudaGetSymbolAddress((void**)&fragP, g_frag);
    cudaGetSymbolAddress((void**)&moeP, g_moe);
    cudaGetSymbolAddress((void**)&a1P, g_a1);
    cudaGetSymbolAddress((void**)&a2P, g_a2);
    cudaGetSymbolAddress((void**)&outsP, g_outs);
    cudaGetSymbolAddress((void**)&molP, g_mol);
    cudaGetSymbolAddress((void**)&wsumP, g_wsum);
    cudaGetSymbolAddress((void**)&listP, g_list);
    cudaGetSymbolAddress((void**)&offsP, g_offs);

    const float inv_std = 0.99999500003749969f; // 1/sqrt(1 + 1e-5)

    const float* cur = x;
    for (int i = 0; i < 3; i++) {
        cudaMemsetAsync(aggP, 0, sizeof(float) * (size_t)NN * DD, 0);
        edge_k<<<NE / 8, 256>>>(edge, edge + NE, cur, aggP);
        gemm_k<0><<<dim3(NN / BM, 1, 1), 256>>>(
            cur, aggP, gin_eps + i,
            gin_w1 + (size_t)i * DD * DD, DD * DD, gin_b1 + (size_t)i * DD, DD,
            nullptr, nullptr, 0.f, tmpP, NN, DD, DD, nullptr, nullptr, 0);
        gemm_k<1><<<dim3(NN / BM, 1, 1), 256>>>(
            tmpP, nullptr, nullptr,
            gin_w2 + (size_t)i * DD * DD, DD * DD, gin_b2 + (size_t)i * DD, DD,
            bn_gamma + (size_t)i * DD, bn_beta + (size_t)i * DD, inv_std,
            hP, NN, DD, DD, nullptr, nullptr, 0);
        cur = hP;
    }

    seg_mean_k<<<NF / 8, 256>>>(hP, node2frag, NN, fragP, NF);
    router_k<<<NF / 8, 256>>>(fragP, gate_w);
    cudaMemsetAsync(wsumP, 0, sizeof(float) * EXP, 0);
    histo_k<<<256, 256>>>();
    scan_k<<<1, 32>>>();
    scatter_k<<<256, 256>>>();

    // expert MLPs on dispatched rows (top-2 only)
    gemm_k<2><<<dim3(NF / BM, HH / BN, EXP), 256>>>(
        fragP, nullptr, nullptr, ew1, DD * HH, eb1, HH,
        nullptr, nullptr, 0.f, a1P, 0, DD, HH, listP, offsP, 1);
    gemm_k<2><<<dim3(NF / BM, HH / BN, EXP), 256>>>(
        a1P, nullptr, nullptr, ew2, HH * HH, eb2, HH,
        nullptr, nullptr, 0.f, a2P, 0, HH, HH, listP, offsP, 0);
    gemm_k<3><<<dim3(NF / BM, DD / BN, EXP), 256>>>(
        a2P, nullptr, nullptr, ew3, HH * DD, eb3, DD,
        nullptr, nullptr, 0.f, outsP, 0, HH, DD, listP, offsP, 0);

    combine_k<<<(NF * 32) / 256, 256>>>();
    seg_mean_k<<<NM / 8, 256>>>(moeP, mol_idx, NF, molP, NM);
    heads_k<<<NM, 64>>>(molP, hw1, hb1, hw2, hb2, (float*)d_out);
    lb_k<<<1, 1>>>((float*)d_out, out_size);
}

// round 2
// speedup vs baseline: 1.2878x; 1.2878x over previous
#include <cuda_runtime.h>
#include <math.h>

#define NN 524288
#define NE 2097152
#define NF 65536
#define NM 8192
#define DD 128
#define HH 256
#define EXP 8
#define NT 3

// ---------------- scratch (device globals; no allocation allowed) -------------
__device__ float g_h[(size_t)NN * DD];
__device__ float g_agg[(size_t)NN * DD];
__device__ float g_frag[(size_t)NF * DD];
__device__ float g_moe[(size_t)NF * DD];
__device__ float g_a1[(size_t)2 * NF * HH];
__device__ float g_a2[(size_t)2 * NF * HH];
__device__ float g_outs[(size_t)2 * NF * DD];
__device__ float g_mol[(size_t)NM * DD];
__device__ int   g_topidx[2 * NF];
__device__ float g_topw[2 * NF];
__device__ int   g_blockcnt[256 * EXP];
__device__ int   g_blockbase[256 * EXP];
__device__ int   g_offs[EXP + 1];
__device__ int   g_list[2 * NF];
__device__ float g_wsum[EXP];

// ---------------- edge scatter-add: agg[dst] += h[src] (vector RED) ----------
__global__ void edge_k(const int* __restrict__ src, const int* __restrict__ dst,
                       const float* __restrict__ h, float* __restrict__ agg)
{
    int e = blockIdx.x * 8 + (threadIdx.x >> 5);
    int c = threadIdx.x & 31;
    if (e >= NE) return;
    int s = src[e];
    int d = dst[e];
    float4 v = ((const float4*)(h + (size_t)s * DD))[c];
    float* ap = agg + (size_t)d * DD + c * 4;
    asm volatile("red.global.add.v4.f32 [%0], {%1, %2, %3, %4};"
                 :: "l"(ap), "f"(v.x), "f"(v.y), "f"(v.z), "f"(v.w) : "memory");
}

// ---------------- fused GIN layer: out = relu(BN(relu(A'@W1+b1)@W2+b2)) ------
// A' = (1+eps)*A + agg. Block: 128 rows x full 128 cols. Hidden kept in smem.
#define GBM 128
#define GBK 16
// dynamic smem layout (floats): As[16][132] | Ws[16][128] | Cs[128][128]
#define S_AS 0
#define S_WS (16 * 132)
#define S_CS (16 * 132 + 16 * 128)
#define GIN_SMEM_FLOATS (16 * 132 + 16 * 128 + 128 * 128)

__global__ void __launch_bounds__(256, 2) gin_fused_k(
    const float* __restrict__ A,
    const float* __restrict__ agg,
    const float* __restrict__ epsP,
    const float* __restrict__ W1, const float* __restrict__ b1,
    const float* __restrict__ W2, const float* __restrict__ b2,
    const float* __restrict__ gmma, const float* __restrict__ bta, float bnscale,
    float* __restrict__ Cout)
{
    extern __shared__ float sm[];
    float* As = sm + S_AS;   // [k][m], stride 132
    float* Ws = sm + S_WS;   // [k][n], stride 128
    float* Cs = sm + S_CS;   // [h][m], stride 128, XOR-swizzled m

    int m0 = blockIdx.x * GBM;
    int tid = threadIdx.x;
    int tx = tid & 15, ty = tid >> 4;

    float acc[8][8];
#pragma unroll
    for (int i = 0; i < 8; i++)
#pragma unroll
        for (int j = 0; j < 8; j++) acc[i][j] = 0.f;

    float alpha = 1.0f + *epsP;

    // ---- GEMM1: acc = A' @ W1 ----
    for (int k0 = 0; k0 < DD; k0 += GBK) {
#pragma unroll
        for (int l = 0; l < 2; l++) {
            int id  = tid + l * 256;       // 0..511
            int row = id >> 2;             // 0..127
            int kq  = (id & 3) * 4;        // 0,4,8,12
            size_t off = (size_t)(m0 + row) * DD + k0 + kq;
            float4 v = *(const float4*)(A + off);
            float4 w = *(const float4*)(agg + off);
            v.x = alpha * v.x + w.x;
            v.y = alpha * v.y + w.y;
            v.z = alpha * v.z + w.z;
            v.w = alpha * v.w + w.w;
            As[(kq + 0) * 132 + row] = v.x;
            As[(kq + 1) * 132 + row] = v.y;
            As[(kq + 2) * 132 + row] = v.z;
            As[(kq + 3) * 132 + row] = v.w;
        }
#pragma unroll
        for (int l = 0; l < 2; l++) {
            int id = tid + l * 256;
            int kr = id >> 5;              // 0..15
            int nq = (id & 31) * 4;
            *(float4*)&Ws[kr * 128 + nq] = *(const float4*)(W1 + (size_t)(k0 + kr) * DD + nq);
        }
        __syncthreads();
#pragma unroll
        for (int kk = 0; kk < GBK; kk++) {
            float a[8], b[8];
            *(float4*)&a[0] = *(const float4*)&As[kk * 132 + ty * 8];
            *(float4*)&a[4] = *(const float4*)&As[kk * 132 + ty * 8 + 4];
            *(float4*)&b[0] = *(const float4*)&Ws[kk * 128 + tx * 8];
            *(float4*)&b[4] = *(const float4*)&Ws[kk * 128 + tx * 8 + 4];
#pragma unroll
            for (int i = 0; i < 8; i++)
#pragma unroll
                for (int j = 0; j < 8; j++) acc[i][j] += a[i] * b[j];
        }
        __syncthreads();
    }

    // ---- epilogue1: relu(acc + b1) -> Cs[n][m] transposed, swizzled ----
    {
        int c = (tx & 7) << 2;
        int mA = (ty * 8) ^ c;
        int mB = (ty * 8 + 4) ^ c;
#pragma unroll
        for (int j = 0; j < 8; j++) {
            int n = tx * 8 + j;
            float bb = b1[n];
            float o[8];
#pragma unroll
            for (int i = 0; i < 8; i++) o[i] = fmaxf(acc[i][j] + bb, 0.f);
            *(float4*)&Cs[n * 128 + mA] = *(float4*)&o[0];
            *(float4*)&Cs[n * 128 + mB] = *(float4*)&o[4];
        }
    }

    // ---- GEMM2: acc = Cs @ W2 ----
#pragma unroll
    for (int i = 0; i < 8; i++)
#pragma unroll
        for (int j = 0; j < 8; j++) acc[i][j] = 0.f;

    for (int k0 = 0; k0 < DD; k0 += GBK) {
        __syncthreads();
#pragma unroll
        for (int l = 0; l < 2; l++) {
            int id = tid + l * 256;
            int kr = id >> 5;
            int nq = (id & 31) * 4;
            *(float4*)&Ws[kr * 128 + nq] = *(const float4*)(W2 + (size_t)(k0 + kr) * DD + nq);
        }
        __syncthreads();
#pragma unroll
        for (int kk = 0; kk < GBK; kk++) {
            int k = k0 + kk;
            int c = ((k >> 3) & 7) << 2;
            float a[8], b[8];
            *(float4*)&a[0] = *(const float4*)&Cs[k * 128 + ((ty * 8) ^ c)];
            *(float4*)&a[4] = *(const float4*)&Cs[k * 128 + ((ty * 8 + 4) ^ c)];
            *(float4*)&b[0] = *(const float4*)&Ws[kk * 128 + tx * 8];
            *(float4*)&b[4] = *(const float4*)&Ws[kk * 128 + tx * 8 + 4];
#pragma unroll
            for (int i = 0; i < 8; i++)
#pragma unroll
                for (int j = 0; j < 8; j++) acc[i][j] += a[i] * b[j];
        }
    }

    // ---- epilogue2: BN + relu -> Cout ----
#pragma unroll
    for (int i = 0; i < 8; i++) {
        int gm = m0 + ty * 8 + i;
        float* cp = Cout + (size_t)gm * DD + tx * 8;
        float o[8];
#pragma unroll
        for (int j = 0; j < 8; j++) {
            int n = tx * 8 + j;
            float v = acc[i][j] + b2[n];
            v = v * (bnscale * gmma[n]) + bta[n];
            o[j] = fmaxf(v, 0.f);
        }
        *(float4*)cp       = *(float4*)&o[0];
        *(float4*)(cp + 4) = *(float4*)&o[4];
    }
}

// ---------------- generic tiled SGEMM with fused epilogues (experts) ---------
#define BM 128
#define BN 128
#define BKK 16

template <int EPI>
__global__ void __launch_bounds__(256, 2) gemm_k(
    const float* __restrict__ A,
    const float* __restrict__ W0, int wStride,
    const float* __restrict__ b0, int bStride,
    float* __restrict__ C,
    int K, int N,
    const int* __restrict__ list, const int* __restrict__ offs, int inShift)
{
    int z = blockIdx.z;
    int base = offs[z];
    int mrows = offs[z + 1] - base;
    const int* lst = list + base;
    int m0 = blockIdx.x * BM;
    if (m0 >= mrows) return;
    int n0 = blockIdx.y * BN;

    const float* W  = W0 + (size_t)z * wStride;
    const float* Bv = b0 + (size_t)z * bStride;

    __shared__ float As[BKK][BM + 4];
    __shared__ float Bs[BKK][BN];

    int tid = threadIdx.x;
    int tx = tid & 15, ty = tid >> 4;

    float acc[8][8];
#pragma unroll
    for (int i = 0; i < 8; i++)
#pragma unroll
        for (int j = 0; j < 8; j++) acc[i][j] = 0.f;

    for (int k0 = 0; k0 < K; k0 += BKK) {
#pragma unroll
        for (int l = 0; l < 2; l++) {
            int id  = tid + l * 256;
            int row = id >> 2;
            int kq  = (id & 3) * 4;
            int gm  = m0 + row;
            float4 v = make_float4(0.f, 0.f, 0.f, 0.f);
            if (gm < mrows) {
                int inRow = lst[gm] >> inShift;
                v = *(const float4*)(A + (size_t)inRow * K + k0 + kq);
            }
            As[kq + 0][row] = v.x;
            As[kq + 1][row] = v.y;
            As[kq + 2][row] = v.z;
            As[kq + 3][row] = v.w;
        }
#pragma unroll
        for (int l = 0; l < 2; l++) {
            int id = tid + l * 256;
            int kr = id >> 5;
            int nq = (id & 31) * 4;
            *(float4*)&Bs[kr][nq] = *(const float4*)(W + (size_t)(k0 + kr) * N + n0 + nq);
        }
        __syncthreads();
#pragma unroll
        for (int kk = 0; kk < BKK; kk++) {
            float a[8], b[8];
            *(float4*)&a[0] = *(const float4*)&As[kk][ty * 8];
            *(float4*)&a[4] = *(const float4*)&As[kk][ty * 8 + 4];
            *(float4*)&b[0] = *(const float4*)&Bs[kk][tx * 8];
            *(float4*)&b[4] = *(const float4*)&Bs[kk][tx * 8 + 4];
#pragma unroll
            for (int i = 0; i < 8; i++)
#pragma unroll
                for (int j = 0; j < 8; j++) acc[i][j] += a[i] * b[j];
        }
        __syncthreads();
    }

#pragma unroll
    for (int i = 0; i < 8; i++) {
        int gm = m0 + ty * 8 + i;
        if (gm >= mrows) continue;
        int outRow = lst[gm];
        float* cp = C + (size_t)outRow * N + n0 + tx * 8;
        float o[8];
#pragma unroll
        for (int j = 0; j < 8; j++) {
            int n = n0 + tx * 8 + j;
            float v = acc[i][j] + Bv[n];
            if (EPI == 2) {
                v = 0.5f * v * (1.f + erff(v * 0.70710678118654752f));
            }
            o[j] = v;
        }
        *(float4*)cp       = *(float4*)&o[0];
        *(float4*)(cp + 4) = *(float4*)&o[4];
    }
}

// ---------------- segment mean (sorted segment ids, warp per segment) --------
__global__ void seg_mean_k(const float* __restrict__ vals, const int* __restrict__ seg,
                           int nItems, float* __restrict__ out, int nSeg)
{
    int w = (blockIdx.x * blockDim.x + threadIdx.x) >> 5;
    int lane = threadIdx.x & 31;
    if (w >= nSeg) return;
    int lo = 0, hi = nItems;
    while (lo < hi) { int mid = (lo + hi) >> 1; if (seg[mid] < w) lo = mid + 1; else hi = mid; }
    int start = lo;
    hi = nItems;
    while (lo < hi) { int mid = (lo + hi) >> 1; if (seg[mid] < w + 1) lo = mid + 1; else hi = mid; }
    int end = lo;
    float4 s = make_float4(0.f, 0.f, 0.f, 0.f);
    for (int r = start; r < end; r++) {
        float4 v = ((const float4*)(vals + (size_t)r * DD))[lane];
        s.x += v.x; s.y += v.y; s.z += v.z; s.w += v.w;
    }
    float inv = 1.f / fmaxf((float)(end - start), 1.f);
    s.x *= inv; s.y *= inv; s.z *= inv; s.w *= inv;
    ((float4*)(out + (size_t)w * DD))[lane] = s;
}

// ---------------- router: logits, top-2, softmax weights ---------------------
__global__ void router_k(const float* __restrict__ frag, const float* __restrict__ gw)
{
    int w = (blockIdx.x * blockDim.x + threadIdx.x) >> 5;
    int lane = threadIdx.x & 31;
    if (w >= NF) return;
    float4 fv = ((const float4*)(frag + (size_t)w * DD))[lane];
    float a[4] = {fv.x, fv.y, fv.z, fv.w};
    float l[EXP];
#pragma unroll
    for (int e = 0; e < EXP; e++) l[e] = 0.f;
    int k0 = lane * 4;
#pragma unroll
    for (int j = 0; j < 4; j++) {
        const float* gr = gw + (k0 + j) * EXP;
#pragma unroll
        for (int e = 0; e < EXP; e++) l[e] += a[j] * gr[e];
    }
#pragma unroll
    for (int off = 16; off; off >>= 1)
#pragma unroll
        for (int e = 0; e < EXP; e++) l[e] += __shfl_down_sync(0xffffffffu, l[e], off);
    if (lane == 0) {
        int i1 = 0;
#pragma unroll
        for (int e = 1; e < EXP; e++) if (l[e] > l[i1]) i1 = e;
        int i2 = (i1 == 0) ? 1 : 0;
#pragma unroll
        for (int e = 0; e < EXP; e++) if (e != i1 && l[e] > l[i2]) i2 = e;
        float d = expf(l[i2] - l[i1]);
        float z = 1.f + d;
        g_topidx[2 * w] = i1;
        g_topidx[2 * w + 1] = i2;
        g_topw[2 * w] = 1.f / z;
        g_topw[2 * w + 1] = d / z;
    }
}

// ---------------- MoE dispatch build: histogram / scan / scatter -------------
__global__ void histo_k()
{
    __shared__ int sc[EXP];
    __shared__ float sw[EXP];
    int t = threadIdx.x, b = blockIdx.x;
    if (t < EXP) { sc[t] = 0; sw[t] = 0.f; }
    __syncthreads();
    int f = b * 256 + t;
    int e0 = g_topidx[2 * f], e1 = g_topidx[2 * f + 1];
    atomicAdd(&sc[e0], 1);
    atomicAdd(&sc[e1], 1);
    atomicAdd(&sw[e0], g_topw[2 * f]);
    atomicAdd(&sw[e1], g_topw[2 * f + 1]);
    __syncthreads();
    if (t < EXP) {
        g_blockcnt[b * EXP + t] = sc[t];
        atomicAdd(&g_wsum[t], sw[t]);
    }
}

__global__ void scan_k()
{
    __shared__ int tot[EXP];
    int e = threadIdx.x;
    if (e < EXP) {
        int s = 0;
        for (int b = 0; b < 256; b++) s += g_blockcnt[b * EXP + e];
        tot[e] = s;
    }
    __syncthreads();
    if (e == 0) {
        int run = 0;
        for (int i = 0; i < EXP; i++) { g_offs[i] = run; run += tot[i]; }
        g_offs[EXP] = run;
    }
    __syncthreads();
    if (e < EXP) {
        int run = g_offs[e];
        for (int b = 0; b < 256; b++) { g_blockbase[b * EXP + e] = run; run += g_blockcnt[b * EXP + e]; }
    }
}

__global__ void scatter_k()
{
    __shared__ int sc[EXP];
    int t = threadIdx.x, b = blockIdx.x;
    if (t < EXP) sc[t] = 0;
    __syncthreads();
    int f = b * 256 + t;
    int e0 = g_topidx[2 * f];
    int p0 = atomicAdd(&sc[e0], 1);
    int e1 = g_topidx[2 * f + 1];
    int p1 = atomicAdd(&sc[e1], 1);
    g_list[g_blockbase[b * EXP + e0] + p0] = 2 * f;
    g_list[g_blockbase[b * EXP + e1] + p1] = 2 * f + 1;
}

// ---------------- combine top-2 expert outputs -------------------------------
__global__ void combine_k()
{
    int t = blockIdx.x * blockDim.x + threadIdx.x;
    int f = t >> 5;
    int c = t & 31;
    float w0 = g_topw[2 * f], w1 = g_topw[2 * f + 1];
    float4 a = ((const float4*)(g_outs + (size_t)(2 * f) * DD))[c];
    float4 b = ((const float4*)(g_outs + (size_t)(2 * f + 1) * DD))[c];
    float4 r;
    r.x = w0 * a.x + w1 * b.x;
    r.y = w0 * a.y + w1 * b.y;
    r.z = w0 * a.z + w1 * b.z;
    r.w = w0 * a.w + w1 * b.w;
    ((float4*)(g_moe + (size_t)f * DD))[c] = r;
}

// ---------------- task heads -------------------------------------------------
__global__ void heads_k(const float* __restrict__ mol,
                        const float* __restrict__ hw1, const float* __restrict__ hb1,
                        const float* __restrict__ hw2, const float* __restrict__ hb2,
                        float* __restrict__ out)
{
    int m = blockIdx.x;
    int j = threadIdx.x; // 64 threads
    __shared__ float emb[DD];
    __shared__ float red[2];
    emb[j] = mol[(size_t)m * DD + j];
    emb[j + 64] = mol[(size_t)m * DD + 64 + j];
    __syncthreads();
    for (int t = 0; t < NT; t++) {
        float p = hb1[t * 64 + j];
        const float* w = hw1 + (size_t)t * DD * 64 + j;
#pragma unroll 4
        for (int d = 0; d < DD; d++) p += emb[d] * w[(size_t)d * 64];
        p = fmaxf(p, 0.f);
        float s = p * hw2[t * 64 + j];
#pragma unroll
        for (int off = 16; off; off >>= 1) s += __shfl_down_sync(0xffffffffu, s, off);
        if ((j & 31) == 0) red[j >> 5] = s;
        __syncthreads();
        if (j == 0) out[m * NT + t] = red[0] + red[1] + hb2[t];
        __syncthreads();
    }
}

// ---------------- load-balance loss ------------------------------------------
__global__ void lb_k(float* __restrict__ out, int out_size)
{
    if (out_size > NM * NT) {
        float s = 0.f;
        for (int e = 0; e < EXP; e++) {
            float l = g_wsum[e] / (float)NF;
            s += l * l;
        }
        out[NM * NT] = (float)EXP * s;
    }
}

// ---------------- launch -----------------------------------------------------
extern "C" void kernel_launch(void* const* d_in, const int* in_sizes, int n_in,
                              void* d_out, int out_size)
{
    const float* x        = (const float*)d_in[0];
    const float* gin_w1   = (const float*)d_in[1];
    const float* gin_b1   = (const float*)d_in[2];
    const float* gin_w2   = (const float*)d_in[3];
    const float* gin_b2   = (const float*)d_in[4];
    const float* gin_eps  = (const float*)d_in[5];
    const float* bn_gamma = (const float*)d_in[6];
    const float* bn_beta  = (const float*)d_in[7];
    const float* gate_w   = (const float*)d_in[8];
    const float* ew1      = (const float*)d_in[9];
    const float* eb1      = (const float*)d_in[10];
    const float* ew2      = (const float*)d_in[11];
    const float* eb2      = (const float*)d_in[12];
    const float* ew3      = (const float*)d_in[13];
    const float* eb3      = (const float*)d_in[14];
    const float* hw1      = (const float*)d_in[15];
    const float* hb1      = (const float*)d_in[16];
    const float* hw2      = (const float*)d_in[17];
    const float* hb2      = (const float*)d_in[18];
    const int*   edge     = (const int*)d_in[19];
    const int*   node2frag= (const int*)d_in[20];
    const int*   mol_idx  = (const int*)d_in[21];
    (void)in_sizes; (void)n_in;

    float *hP, *aggP, *fragP, *moeP, *a1P, *a2P, *outsP, *molP, *wsumP;
    int *listP, *offsP;
    cudaGetSymbolAddress((void**)&hP, g_h);
    cudaGetSymbolAddress((void**)&aggP, g_agg);
    cudaGetSymbolAddress((void**)&fragP, g_frag);
    cudaGetSymbolAddress((void**)&moeP, g_moe);
    cudaGetSymbolAddress((void**)&a1P, g_a1);
    cudaGetSymbolAddress((void**)&a2P, g_a2);
    cudaGetSymbolAddress((void**)&outsP, g_outs);
    cudaGetSymbolAddress((void**)&molP, g_mol);
    cudaGetSymbolAddress((void**)&wsumP, g_wsum);
    cudaGetSymbolAddress((void**)&listP, g_list);
    cudaGetSymbolAddress((void**)&offsP, g_offs);

    static int smem_set = 0;
    cudaFuncSetAttribute(gin_fused_k, cudaFuncAttributeMaxDynamicSharedMemorySize,
                         GIN_SMEM_FLOATS * (int)sizeof(float));
    (void)smem_set;

    const float inv_std = 0.99999500003749969f; // 1/sqrt(1 + 1e-5)

    const float* cur = x;
    for (int i = 0; i < 3; i++) {
        cudaMemsetAsync(aggP, 0, sizeof(float) * (size_t)NN * DD, 0);
        edge_k<<<NE / 8, 256>>>(edge, edge + NE, cur, aggP);
        gin_fused_k<<<NN / GBM, 256, GIN_SMEM_FLOATS * sizeof(float)>>>(
            cur, aggP, gin_eps + i,
            gin_w1 + (size_t)i * DD * DD, gin_b1 + (size_t)i * DD,
            gin_w2 + (size_t)i * DD * DD, gin_b2 + (size_t)i * DD,
            bn_gamma + (size_t)i * DD, bn_beta + (size_t)i * DD, inv_std,
            hP);
        cur = hP;
    }

    seg_mean_k<<<NF / 8, 256>>>(hP, node2frag, NN, fragP, NF);
    router_k<<<NF / 8, 256>>>(fragP, gate_w);
    cudaMemsetAsync(wsumP, 0, sizeof(float) * EXP, 0);
    histo_k<<<256, 256>>>();
    scan_k<<<1, 32>>>();
    scatter_k<<<256, 256>>>();

    // expert MLPs on dispatched rows (top-2 only)
    gemm_k<2><<<dim3(NF / BM, HH / BN, EXP), 256>>>(
        fragP, ew1, DD * HH, eb1, HH, a1P, DD, HH, listP, offsP, 1);
    gemm_k<2><<<dim3(NF / BM, HH / BN, EXP), 256>>>(
        a1P, ew2, HH * HH, eb2, HH, a2P, HH, HH, listP, offsP, 0);
    gemm_k<3><<<dim3(NF / BM, DD / BN, EXP), 256>>>(
        a2P, ew3, HH * DD, eb3, DD, outsP, HH, DD, listP, offsP, 0);

    combine_k<<<(NF * 32) / 256, 256>>>();
    seg_mean_k<<<NM / 8, 256>>>(moeP, mol_idx, NF, molP, NM);
    heads_k<<<NM, 64>>>(molP, hw1, hb1, hw2, hb2, (float*)d_out);
    lb_k<<<1, 1>>>((float*)d_out, out_size);
}